// round 3
// baseline (speedup 1.0000x reference)
#include <cuda_runtime.h>

#define HH 128
#define WW 128
#define CC 64
#define NHEAD 8
#define HD 8
#define NTOK 256
#define NTHREADS 64

// ---- f32x2 packed-math helpers (sm_103a; ptxas will not auto-fuse these) ----
__device__ __forceinline__ unsigned long long f2pack(float lo, float hi) {
    unsigned long long r;
    asm("mov.b64 %0, {%1,%2};" : "=l"(r) : "f"(lo), "f"(hi));
    return r;
}
__device__ __forceinline__ void f2unpack(unsigned long long a, float &lo, float &hi) {
    asm("mov.b64 {%0,%1}, %2;" : "=f"(lo), "=f"(hi) : "l"(a));
}
__device__ __forceinline__ unsigned long long ffma2(unsigned long long a,
                                                    unsigned long long b,
                                                    unsigned long long c) {
    unsigned long long r;
    asm("fma.rn.f32x2 %0, %1, %2, %3;" : "=l"(r) : "l"(a), "l"(b), "l"(c));
    return r;
}
__device__ __forceinline__ float ex2f(float x) {
    float y; asm("ex2.approx.f32 %0, %1;" : "=f"(y) : "f"(x)); return y;
}

// One CTA = one (batch, window, head). 64 threads, 4 tokens each.
// Tokens: n = h*2 + ws; thread t owns h = t and h = t+64, both ws.
__global__ __launch_bounds__(NTHREADS) void lepe_kernel(
    const float* __restrict__ temp,   // (B,3,C,H,W) fp32
    const float* __restrict__ convw,  // (C,1,3,3)
    const float* __restrict__ convb,  // (C,)
    float* __restrict__ out)          // (B, H*W, C)
{
    const int wi   = blockIdx.x & 63;         // window (fastest -> L2 sector sharing)
    const int head = (blockIdx.x >> 6) & 7;
    const int b    = blockIdx.x >> 9;
    const int t    = threadIdx.x;

    __shared__ float2 Kdup[HD][NTOK];   // K duplicated (k,k), d-major: broadcast LDS.64
    __shared__ float  Vrow[NTOK][HD];   // V token-major: packed-d LDS.64
    __shared__ float  Wc[HD][9];
    __shared__ float  Bc[HD];

    const size_t plane = (size_t)HH * WW;                    // 16384
    const float* qb = temp + ((size_t)b * 3 + 0) * CC * plane;
    const float* kb = temp + ((size_t)b * 3 + 1) * CC * plane;
    const float* vb = temp + ((size_t)b * 3 + 2) * CC * plane;
    const int colw = 2 * wi;

    // fold softmax scale (hd^-0.5) and log2(e) into Q -> exp via single EX2
    const float C1 = 0.35355339059327373f * 1.4426950408889634f;

    // ---- load Q (regs) / K,V (smem) ----
    float q[4][HD];
    #pragma unroll
    for (int r = 0; r < 2; r++) {
        const int h = t + r * 64;
        const size_t sp = (size_t)h * WW + colw;
        #pragma unroll
        for (int d = 0; d < HD; d++) {
            const int c = head * HD + d;
            const float2 qq = *(const float2*)(qb + c * plane + sp);
            q[2*r  ][d] = qq.x * C1;
            q[2*r+1][d] = qq.y * C1;
            const float2 kk = *(const float2*)(kb + c * plane + sp);
            Kdup[d][2*h  ] = make_float2(kk.x, kk.x);
            Kdup[d][2*h+1] = make_float2(kk.y, kk.y);
            const float2 vv = *(const float2*)(vb + c * plane + sp);
            Vrow[2*h  ][d] = vv.x;
            Vrow[2*h+1][d] = vv.y;
        }
    }
    // FIX (R2 bug): HD*9 = 72 > 64 threads -> strided loop, not a guard
    for (int i = t; i < HD * 9; i += NTHREADS)
        Wc[i / 9][i % 9] = convw[(head * HD + i / 9) * 9 + (i % 9)];
    if (t < HD) Bc[t] = convb[head * HD + t];
    __syncthreads();

    // pack Q across row-pairs: (row0,row1), (row2,row3)
    unsigned long long q01[HD], q23[HD];
    #pragma unroll
    for (int d = 0; d < HD; d++) {
        q01[d] = f2pack(q[0][d], q[1][d]);
        q23[d] = f2pack(q[2][d], q[3][d]);
    }

    unsigned long long o[4][4];   // per row: 4 f32x2 accumulators over d
    #pragma unroll
    for (int r = 0; r < 4; r++)
        #pragma unroll
        for (int c = 0; c < 4; c++) o[r][c] = 0ULL;
    float l[4] = {0.f, 0.f, 0.f, 0.f};

    const unsigned long long* KdU = (const unsigned long long*)(&Kdup[0][0]);
    const unsigned long long* VrU = (const unsigned long long*)(&Vrow[0][0]);

    // ---- main loop: online softmax (no max tracking: |s| is small, exp2 safe) ----
    #pragma unroll 2
    for (int j = 0; j < NTOK; j++) {
        unsigned long long kd[HD];
        #pragma unroll
        for (int d = 0; d < HD; d++) kd[d] = KdU[d * NTOK + j];

        unsigned long long s01 = 0ULL, s23 = 0ULL;   // (0.0f, 0.0f)
        #pragma unroll
        for (int d = 0; d < HD; d++) {
            s01 = ffma2(q01[d], kd[d], s01);
            s23 = ffma2(q23[d], kd[d], s23);
        }
        float s0, s1, s2, s3;
        f2unpack(s01, s0, s1);
        f2unpack(s23, s2, s3);
        const float p0 = ex2f(s0), p1 = ex2f(s1), p2 = ex2f(s2), p3 = ex2f(s3);
        l[0] += p0; l[1] += p1; l[2] += p2; l[3] += p3;

        const unsigned long long pp0 = f2pack(p0, p0), pp1 = f2pack(p1, p1),
                                 pp2 = f2pack(p2, p2), pp3 = f2pack(p3, p3);
        unsigned long long v2[4];
        #pragma unroll
        for (int c = 0; c < 4; c++) v2[c] = VrU[j * 4 + c];
        #pragma unroll
        for (int c = 0; c < 4; c++) {
            o[0][c] = ffma2(pp0, v2[c], o[0][c]);
            o[1][c] = ffma2(pp1, v2[c], o[1][c]);
            o[2][c] = ffma2(pp2, v2[c], o[2][c]);
            o[3][c] = ffma2(pp3, v2[c], o[3][c]);
        }
    }

    // ---- epilogue: normalize, fused depthwise 3x3 (LePE) on V, store ----
    #pragma unroll
    for (int r = 0; r < 4; r++) {
        const int h  = (r < 2) ? t : (t + 64);
        const int ws = r & 1;
        const float inv = 1.0f / l[r];
        float ov[8];
        #pragma unroll
        for (int c = 0; c < 4; c++) {
            float lo, hi; f2unpack(o[r][c], lo, hi);
            ov[2*c] = lo * inv; ov[2*c+1] = hi * inv;
        }
        // rpe: cross-correlation 3x3 SAME on the 128x2 window, per channel
        #pragma unroll
        for (int d = 0; d < HD; d++) {
            float acc = Bc[d];
            #pragma unroll
            for (int dh = -1; dh <= 1; dh++) {
                const int hh = h + dh;
                if (hh >= 0 && hh < HH) {
                    const float va  = Vrow[2*hh  ][d];   // ws' = 0
                    const float vb2 = Vrow[2*hh+1][d];   // ws' = 1
                    if (ws == 0)
                        acc += Wc[d][(dh+1)*3 + 1] * va + Wc[d][(dh+1)*3 + 2] * vb2;
                    else
                        acc += Wc[d][(dh+1)*3 + 0] * va + Wc[d][(dh+1)*3 + 1] * vb2;
                }
            }
            ov[d] += acc;
        }
        const size_t ob = (((size_t)b * plane) + (size_t)h * WW + (colw + ws)) * CC
                          + (size_t)head * HD;
        float4* op = (float4*)(out + ob);
        op[0] = make_float4(ov[0], ov[1], ov[2], ov[3]);
        op[1] = make_float4(ov[4], ov[5], ov[6], ov[7]);
    }
}

extern "C" void kernel_launch(void* const* d_in, const int* in_sizes, int n_in,
                              void* d_out, int out_size) {
    const float* temp = (const float*)d_in[0];
    const float* cw   = (const float*)d_in[1];
    const float* cb   = (const float*)d_in[2];
    float* out        = (float*)d_out;
    (void)in_sizes; (void)n_in; (void)out_size;
    lepe_kernel<<<4 * 64 * 8, NTHREADS>>>(temp, cw, cb, out);
}